// round 14
// baseline (speedup 1.0000x reference)
#include <cuda_runtime.h>
#include <cuda_bf16.h>
#include <cstdint>
#include <math.h>

#define NN   50000
#define HID  128
#define EF   800000
#define EP   400000

// ---------------- float scratch layout ----------------
constexpr long F_H    = 0;
constexpr long F_HSF  = F_H    + (long)NN * HID;
constexpr long F_HDF  = F_HSF  + (long)NN * HID;
constexpr long F_HSP  = F_HDF  + (long)NN * HID;
constexpr long F_HDP  = F_HSP  + (long)NN * HID;
constexpr long F_OUTF = F_HDP  + (long)NN * HID;
constexpr long F_OUTP = F_OUTF + (long)NN * HID;
constexpr long F_LOGF = F_OUTP + (long)NN * HID;
constexpr long F_LOGP = F_LOGF + 4L * EF;
constexpr long F_TOT  = F_LOGP + 4L * EP;

// ---------------- int scratch layout -------------------
constexpr long I_DEGF = 0;
constexpr long I_OFFF = I_DEGF + NN;
constexpr long I_CURF = I_OFFF + NN;
constexpr long I_DEGP = I_CURF + NN;
constexpr long I_OFFP = I_DEGP + NN;
constexpr long I_CURP = I_OFFP + NN;
constexpr long I_EIDF = I_CURP + NN;
constexpr long I_EIDP = I_EIDF + (long)EF;
constexpr long I_TOT  = I_EIDP + (long)EP;

__device__ float g_f[F_TOT];
__device__ int   g_i[I_TOT];

// ---------------- helpers ----------------
__device__ __forceinline__ uint32_t f2tf(float x) {
    uint32_t r;
    asm("cvt.rna.tf32.f32 %0, %1;" : "=r"(r) : "f"(x));
    return r;
}

__device__ __forceinline__ void split_tf(float x, uint32_t& hi, uint32_t& lo) {
    hi = f2tf(x);
    float r = x - __uint_as_float(hi);
    lo = f2tf(r);
}

__device__ __forceinline__ void mma8(float* c, const uint32_t* a, const uint32_t* b) {
    asm volatile(
        "mma.sync.aligned.m16n8k8.row.col.f32.tf32.tf32.f32 "
        "{%0,%1,%2,%3}, {%4,%5,%6,%7}, {%8,%9}, {%0,%1,%2,%3};\n"
        : "+f"(c[0]), "+f"(c[1]), "+f"(c[2]), "+f"(c[3])
        : "r"(a[0]), "r"(a[1]), "r"(a[2]), "r"(a[3]),
          "r"(b[0]), "r"(b[1]));
}

__device__ __forceinline__ void cp16(uint32_t dst, const void* src, bool p) {
    int sz = p ? 16 : 0;
    asm volatile("cp.async.ca.shared.global [%0], [%1], 16, %2;\n"
                 :: "r"(dst), "l"(src), "r"(sz));
}

__device__ __forceinline__ uint32_t sptr(const void* p) {
    return (uint32_t)__cvta_generic_to_shared(p);
}

// ============================================================
// GEMM: C[M,128] = A[M,K] @ B[K,128] (+bias), split-TF32
// CTA = 128x128 tile, 8 warps of 32x64, double-buffered cp.async.
// As: [128 rows][stride 20]  (16B-aligned rows, conflict-free frag loads)
// Bs: [16 rows][stride 132]
// ============================================================
__global__ void __launch_bounds__(256) gemm128(
    const float* __restrict__ Aext, long a_off,
    const float* __restrict__ B,
    const float* __restrict__ bias,
    long c_off, int M, int K)
{
    const float* A = Aext ? Aext : (g_f + a_off);
    float* C = g_f + c_off;

    __shared__ float As[2][128 * 20];
    __shared__ float Bs[2][16 * 132];

    int tid  = threadIdx.x;
    int warp = tid >> 5, lane = tid & 31;
    int wm = warp >> 1;        // 0..3
    int wn = warp & 1;         // 0..1
    int m_blk = blockIdx.x * 128;

    float c[2][8][4];
#pragma unroll
    for (int i = 0; i < 2; i++)
#pragma unroll
        for (int j = 0; j < 8; j++)
#pragma unroll
            for (int k = 0; k < 4; k++) c[i][j][k] = 0.f;

    int steps = K >> 4;

    // ---- prologue load ----
    {
        int k0 = 0;
#pragma unroll
        for (int c2 = 0; c2 < 2; c2++) {
            int ch = tid + c2 * 256;
            int row = ch >> 2, j = ch & 3;
            bool ok = (m_blk + row) < M;
            long grow = ok ? (long)(m_blk + row) : 0;
            cp16(sptr(&As[0][row * 20 + j * 4]), A + grow * K + k0 + j * 4, ok);
        }
#pragma unroll
        for (int c2 = 0; c2 < 2; c2++) {
            int ch = tid + c2 * 256;
            int row = ch >> 5, j = ch & 31;
            cp16(sptr(&Bs[0][row * 132 + j * 4]), B + (long)(k0 + row) * 128 + j * 4, true);
        }
        asm volatile("cp.async.commit_group;\n");
    }

    for (int kt = 0; kt < steps; kt++) {
        int b = kt & 1;
        if (kt + 1 < steps) {
            int k0 = (kt + 1) * 16;
            int nb = b ^ 1;
#pragma unroll
            for (int c2 = 0; c2 < 2; c2++) {
                int ch = tid + c2 * 256;
                int row = ch >> 2, j = ch & 3;
                bool ok = (m_blk + row) < M;
                long grow = ok ? (long)(m_blk + row) : 0;
                cp16(sptr(&As[nb][row * 20 + j * 4]), A + grow * K + k0 + j * 4, ok);
            }
#pragma unroll
            for (int c2 = 0; c2 < 2; c2++) {
                int ch = tid + c2 * 256;
                int row = ch >> 5, j = ch & 31;
                cp16(sptr(&Bs[nb][row * 132 + j * 4]), B + (long)(k0 + row) * 128 + j * 4, true);
            }
            asm volatile("cp.async.commit_group;\n");
            asm volatile("cp.async.wait_group 1;\n");
        } else {
            asm volatile("cp.async.wait_group 0;\n");
        }
        __syncthreads();

        // ---- compute on buffer b ----
#pragma unroll
        for (int ks = 0; ks < 2; ks++) {
            int k0 = ks * 8;
            int kk = k0 + (lane & 3);
            uint32_t ah[2][4], al[2][4];
#pragma unroll
            for (int mi = 0; mi < 2; mi++) {
                int r = wm * 32 + mi * 16 + (lane >> 2);
                float a0 = As[b][r * 20 + kk];
                float a1 = As[b][(r + 8) * 20 + kk];
                float a2 = As[b][r * 20 + kk + 4];
                float a3 = As[b][(r + 8) * 20 + kk + 4];
                split_tf(a0, ah[mi][0], al[mi][0]);
                split_tf(a1, ah[mi][1], al[mi][1]);
                split_tf(a2, ah[mi][2], al[mi][2]);
                split_tf(a3, ah[mi][3], al[mi][3]);
            }
#pragma unroll
            for (int ni = 0; ni < 8; ni++) {
                int col = wn * 64 + ni * 8 + (lane >> 2);
                float b0f = Bs[b][kk * 132 + col];
                float b1f = Bs[b][(kk + 4) * 132 + col];
                uint32_t bh[2], bl[2];
                split_tf(b0f, bh[0], bl[0]);
                split_tf(b1f, bh[1], bl[1]);
#pragma unroll
                for (int mi = 0; mi < 2; mi++) {
                    mma8(c[mi][ni], ah[mi], bh);
                    mma8(c[mi][ni], al[mi], bh);
                    mma8(c[mi][ni], ah[mi], bl);
                }
            }
        }
        __syncthreads();
    }

    // ---- epilogue ----
#pragma unroll
    for (int mi = 0; mi < 2; mi++) {
#pragma unroll
        for (int ni = 0; ni < 8; ni++) {
            int col = wn * 64 + ni * 8 + (lane & 3) * 2;
            float bb0 = bias ? bias[col] : 0.f;
            float bb1 = bias ? bias[col + 1] : 0.f;
            int r0 = m_blk + wm * 32 + mi * 16 + (lane >> 2);
            if (r0 < M) {
                float2 v = make_float2(c[mi][ni][0] + bb0, c[mi][ni][1] + bb1);
                *(float2*)(C + (long)r0 * 128 + col) = v;
            }
            int r1 = r0 + 8;
            if (r1 < M) {
                float2 v = make_float2(c[mi][ni][2] + bb0, c[mi][ni][3] + bb1);
                *(float2*)(C + (long)r1 * 128 + col) = v;
            }
        }
    }
}

// ============================================================
// CSR build
// ============================================================
__global__ void zero_ints(long off, int n) {
    int i = blockIdx.x * blockDim.x + threadIdx.x;
    if (i < n) g_i[off + i] = 0;
}

__global__ void count_deg(const int* __restrict__ ei, int E, long deg_off) {
    int e = blockIdx.x * blockDim.x + threadIdx.x;
    if (e < E) atomicAdd(&g_i[deg_off + ei[E + e]], 1);
}

__global__ void scan_deg(long deg_off, long off_off, long cur_off, int n) {
    __shared__ int ssum[1024];
    int t = threadIdx.x;
    int C = (n + 1023) / 1024;
    int lo = t * C, hi = min(n, (t + 1) * C);
    int s = 0;
    for (int i = lo; i < hi; i++) s += g_i[deg_off + i];
    ssum[t] = s;
    __syncthreads();
    for (int d = 1; d < 1024; d <<= 1) {
        int v = (t >= d) ? ssum[t - d] : 0;
        __syncthreads();
        ssum[t] += v;
        __syncthreads();
    }
    int run = (t == 0) ? 0 : ssum[t - 1];
    for (int i = lo; i < hi; i++) {
        g_i[off_off + i] = run;
        g_i[cur_off + i] = run;
        run += g_i[deg_off + i];
    }
}

__global__ void fill_csr(const int* __restrict__ ei, int E, long cur_off, long eid_off) {
    int e = blockIdx.x * blockDim.x + threadIdx.x;
    if (e >= E) return;
    int d = ei[E + e];
    int pos = atomicAdd(&g_i[cur_off + d], 1);
    g_i[eid_off + pos] = e;
}

// ============================================================
// GATv2: one warp per destination node.
// ============================================================
__global__ void __launch_bounds__(256) gat_kernel(
    long hs_off, long hd_off,
    long off_off, long deg_off, long eid_off,
    const int* __restrict__ edge_index,   // [2,E]; row0 = src
    int E,
    const float* __restrict__ edge_w,     // [E]
    const float* __restrict__ wedge,      // [128]
    const float* __restrict__ attn,       // [4,32]
    const float* __restrict__ bias,       // [128]
    long logits_off, long out_off)
{
    const float* hs   = g_f + hs_off;
    const float* hd   = g_f + hd_off;
    const int*   off  = g_i + off_off;
    const int*   degv = g_i + deg_off;
    const int*   eid  = g_i + eid_off;
    float* logits = g_f + logits_off;
    float* out    = g_f + out_off;

    int gw = (blockIdx.x * blockDim.x + threadIdx.x) >> 5;
    if (gw >= NN) return;
    int lane = threadIdx.x & 31;
    int n = gw;
    int begin = off[n];
    int end = begin + degv[n];

    float4 hdv = *(const float4*)(hd + (long)n * 128 + lane * 4);
    float4 wev = *(const float4*)(wedge + lane * 4);
    int h8 = lane >> 3;                          // head this oct handles
    float4 av = *(const float4*)(attn + h8 * 32 + (lane & 7) * 4);

    float maxv = -3.402823466e38f;

    // pass 1: logits + max
    for (int p = begin; p < end; p++) {
        int e = eid[p];
        int s = edge_index[e];
        float w = edge_w[e];
        float4 hsv = *(const float4*)(hs + (long)s * 128 + lane * 4);
        float z0 = hsv.x + hdv.x + w * wev.x; z0 = z0 > 0.f ? z0 : 0.2f * z0;
        float z1 = hsv.y + hdv.y + w * wev.y; z1 = z1 > 0.f ? z1 : 0.2f * z1;
        float z2 = hsv.z + hdv.z + w * wev.z; z2 = z2 > 0.f ? z2 : 0.2f * z2;
        float z3 = hsv.w + hdv.w + w * wev.w; z3 = z3 > 0.f ? z3 : 0.2f * z3;
        float part = av.x * z0 + av.y * z1 + av.z * z2 + av.w * z3;
        part += __shfl_xor_sync(0xffffffffu, part, 4);
        part += __shfl_xor_sync(0xffffffffu, part, 2);
        part += __shfl_xor_sync(0xffffffffu, part, 1);
        if ((lane & 7) == 0) logits[(long)p * 4 + h8] = part;
        maxv = fmaxf(maxv, part);
    }

    float m0 = __shfl_sync(0xffffffffu, maxv, 0);
    float m1 = __shfl_sync(0xffffffffu, maxv, 8);
    float m2 = __shfl_sync(0xffffffffu, maxv, 16);
    float m3 = __shfl_sync(0xffffffffu, maxv, 24);

    // pass 2: sumexp (lane l handles head l&3, positions strided by 8)
    int h4 = lane & 3;
    float mh4 = h4 == 0 ? m0 : h4 == 1 ? m1 : h4 == 2 ? m2 : m3;
    float se = 0.f;
    for (int p = begin + (lane >> 2); p < end; p += 8)
        se += expf(logits[(long)p * 4 + h4] - mh4);
    se += __shfl_xor_sync(0xffffffffu, se, 16);
    se += __shfl_xor_sync(0xffffffffu, se, 8);
    se += __shfl_xor_sync(0xffffffffu, se, 4);
    float s0 = __shfl_sync(0xffffffffu, se, 0);
    float s1 = __shfl_sync(0xffffffffu, se, 1);
    float s2 = __shfl_sync(0xffffffffu, se, 2);
    float s3 = __shfl_sync(0xffffffffu, se, 3);

    float mh8 = h8 == 0 ? m0 : h8 == 1 ? m1 : h8 == 2 ? m2 : m3;
    float sh8 = h8 == 0 ? s0 : h8 == 1 ? s1 : h8 == 2 ? s2 : s3;
    float inv = 1.f / (sh8 + 1e-16f);

    // pass 3: weighted aggregate
    float a0 = 0.f, a1 = 0.f, a2 = 0.f, a3 = 0.f;
    for (int p = begin; p < end; p++) {
        int e = eid[p];
        int s = edge_index[e];
        float lg = logits[(long)p * 4 + h8];
        float att = expf(lg - mh8) * inv;
        float4 hsv = *(const float4*)(hs + (long)s * 128 + lane * 4);
        a0 += att * hsv.x; a1 += att * hsv.y;
        a2 += att * hsv.z; a3 += att * hsv.w;
    }
    float4 o = make_float4(a0 + bias[lane * 4], a1 + bias[lane * 4 + 1],
                           a2 + bias[lane * 4 + 2], a3 + bias[lane * 4 + 3]);
    *(float4*)(out + (long)n * 128 + lane * 4) = o;
}

// ============================================================
// combine + ELU + LayerNorm: one warp per row
// ============================================================
__global__ void __launch_bounds__(256) combine_ln(
    const float* __restrict__ alpha,
    const float* __restrict__ ln_scale,
    const float* __restrict__ ln_bias,
    float* __restrict__ out)
{
    int gw = (blockIdx.x * blockDim.x + threadIdx.x) >> 5;
    if (gw >= NN) return;
    int lane = threadIdx.x & 31;
    float a = *alpha;
    const float* hf = g_f + F_OUTF + (long)gw * 128;
    const float* hp = g_f + F_OUTP + (long)gw * 128;

    float x[4];
#pragma unroll
    for (int i = 0; i < 4; i++) {
        float v = (1.f - a) * hf[lane * 4 + i] + a * hp[lane * 4 + i];
        x[i] = v > 0.f ? v : expm1f(v);
    }
    float s = x[0] + x[1] + x[2] + x[3];
#pragma unroll
    for (int o = 16; o > 0; o >>= 1) s += __shfl_xor_sync(0xffffffffu, s, o);
    float mu = s * (1.f / 128.f);
    float vs = 0.f;
#pragma unroll
    for (int i = 0; i < 4; i++) { float d = x[i] - mu; vs += d * d; }
#pragma unroll
    for (int o = 16; o > 0; o >>= 1) vs += __shfl_xor_sync(0xffffffffu, vs, o);
    float r = rsqrtf(vs * (1.f / 128.f) + 1e-6f);
#pragma unroll
    for (int i = 0; i < 4; i++) {
        int col = lane * 4 + i;
        out[(long)gw * 128 + col] = (x[i] - mu) * r * ln_scale[col] + ln_bias[col];
    }
}

// ============================================================
extern "C" void kernel_launch(void* const* d_in, const int* in_sizes, int n_in,
                              void* d_out, int out_size) {
    const float* X       = (const float*)d_in[0];
    const int*   eif     = (const int*)  d_in[1];
    const float* ewf     = (const float*)d_in[2];
    const int*   eip     = (const int*)  d_in[3];
    const float* ewp     = (const float*)d_in[4];
    const float* alpha   = (const float*)d_in[5];
    const float* ip_w    = (const float*)d_in[6];
    const float* ip_b    = (const float*)d_in[7];
    const float* gf_wsrc = (const float*)d_in[8];
    const float* gf_wdst = (const float*)d_in[9];
    const float* gf_wedge= (const float*)d_in[10];
    const float* gf_attn = (const float*)d_in[11];
    const float* gf_bias = (const float*)d_in[12];
    const float* gp_wsrc = (const float*)d_in[13];
    const float* gp_wdst = (const float*)d_in[14];
    const float* gp_wedge= (const float*)d_in[15];
    const float* gp_attn = (const float*)d_in[16];
    const float* gp_bias = (const float*)d_in[17];
    const float* ln_scale= (const float*)d_in[18];
    const float* ln_bias = (const float*)d_in[19];
    float* out = (float*)d_out;

    int gm = (NN + 127) / 128;   // 391

    // input projection + the 4 h-projections
    gemm128<<<gm, 256>>>(X, 0, ip_w, ip_b, F_H, NN, 2000);
    gemm128<<<gm, 256>>>(nullptr, F_H, gf_wsrc, nullptr, F_HSF, NN, 128);
    gemm128<<<gm, 256>>>(nullptr, F_H, gf_wdst, nullptr, F_HDF, NN, 128);
    gemm128<<<gm, 256>>>(nullptr, F_H, gp_wsrc, nullptr, F_HSP, NN, 128);
    gemm128<<<gm, 256>>>(nullptr, F_H, gp_wdst, nullptr, F_HDP, NN, 128);

    // CSR build (both graphs)
    int gz = (NN + 255) / 256;
    zero_ints<<<gz, 256>>>(I_DEGF, NN);
    zero_ints<<<gz, 256>>>(I_DEGP, NN);
    count_deg<<<(EF + 255) / 256, 256>>>(eif, EF, I_DEGF);
    count_deg<<<(EP + 255) / 256, 256>>>(eip, EP, I_DEGP);
    scan_deg<<<1, 1024>>>(I_DEGF, I_OFFF, I_CURF, NN);
    scan_deg<<<1, 1024>>>(I_DEGP, I_OFFP, I_CURP, NN);
    fill_csr<<<(EF + 255) / 256, 256>>>(eif, EF, I_CURF, I_EIDF);
    fill_csr<<<(EP + 255) / 256, 256>>>(eip, EP, I_CURP, I_EIDP);

    // GATv2 on both graphs
    int gg = (NN * 32 + 255) / 256;
    gat_kernel<<<gg, 256>>>(F_HSF, F_HDF, I_OFFF, I_DEGF, I_EIDF,
                            eif, EF, ewf, gf_wedge, gf_attn, gf_bias,
                            F_LOGF, F_OUTF);
    gat_kernel<<<gg, 256>>>(F_HSP, F_HDP, I_OFFP, I_DEGP, I_EIDP,
                            eip, EP, ewp, gp_wedge, gp_attn, gp_bias,
                            F_LOGP, F_OUTP);

    // combine + elu + layernorm
    combine_ln<<<gg, 256>>>(alpha, ln_scale, ln_bias, out);
}

// round 15
// speedup vs baseline: 1.0728x; 1.0728x over previous
#include <cuda_runtime.h>
#include <cuda_bf16.h>
#include <cstdint>
#include <math.h>

#define NN   50000
#define HID  128
#define EF   800000
#define EP   400000

// ---------------- float scratch layout ----------------
constexpr long F_H    = 0;
constexpr long F_HSF  = F_H    + (long)NN * HID;
constexpr long F_HDF  = F_HSF  + (long)NN * HID;   // must stay contiguous:
constexpr long F_HSP  = F_HDF  + (long)NN * HID;   // batched GEMM writes
constexpr long F_HDP  = F_HSP  + (long)NN * HID;   // HSF,HDF,HSP,HDP via blockIdx.y
constexpr long F_OUTF = F_HDP  + (long)NN * HID;
constexpr long F_OUTP = F_OUTF + (long)NN * HID;
constexpr long F_WF   = F_OUTP + (long)NN * HID;   // permuted edge weights (full)
constexpr long F_WP   = F_WF   + (long)EF;
constexpr long F_TOT  = F_WP   + (long)EP;

// ---------------- int scratch layout -------------------
constexpr long I_DEGF = 0;
constexpr long I_OFFF = I_DEGF + NN;
constexpr long I_CURF = I_OFFF + NN;
constexpr long I_DEGP = I_CURF + NN;
constexpr long I_OFFP = I_DEGP + NN;
constexpr long I_CURP = I_OFFP + NN;
constexpr long I_SRCF = I_CURP + NN;               // permuted src ids
constexpr long I_SRCP = I_SRCF + (long)EF;
constexpr long I_TOT  = I_SRCP + (long)EP;

__device__ float g_f[F_TOT];
__device__ int   g_i[I_TOT];

// ---------------- helpers ----------------
__device__ __forceinline__ uint32_t f2tf(float x) {
    uint32_t r;
    asm("cvt.rna.tf32.f32 %0, %1;" : "=r"(r) : "f"(x));
    return r;
}

__device__ __forceinline__ void split_tf(float x, uint32_t& hi, uint32_t& lo) {
    hi = f2tf(x);
    float r = x - __uint_as_float(hi);
    lo = f2tf(r);
}

__device__ __forceinline__ void mma8(float* c, const uint32_t* a, const uint32_t* b) {
    asm volatile(
        "mma.sync.aligned.m16n8k8.row.col.f32.tf32.tf32.f32 "
        "{%0,%1,%2,%3}, {%4,%5,%6,%7}, {%8,%9}, {%0,%1,%2,%3};\n"
        : "+f"(c[0]), "+f"(c[1]), "+f"(c[2]), "+f"(c[3])
        : "r"(a[0]), "r"(a[1]), "r"(a[2]), "r"(a[3]),
          "r"(b[0]), "r"(b[1]));
}

__device__ __forceinline__ void cp16(uint32_t dst, const void* src, bool p) {
    int sz = p ? 16 : 0;
    asm volatile("cp.async.ca.shared.global [%0], [%1], 16, %2;\n"
                 :: "r"(dst), "l"(src), "r"(sz));
}

__device__ __forceinline__ uint32_t sptr(const void* p) {
    return (uint32_t)__cvta_generic_to_shared(p);
}

// ============================================================
// GEMM: C[M,128] = A[M,K] @ Bsel[K,128] (+bias), split-TF32
// CTA = 128x128 tile, 8 warps of 32x64, double-buffered cp.async.
// gridDim.y selects among up to 4 B matrices; C advances by NN*HID per y.
// As: [128][20]  Bs: [16][136] (conflict-free B fragment loads)
// __launch_bounds__(256,2): 2 CTAs/SM (16 warps) for latency hiding.
// ============================================================
#define LDBS 136

__global__ void __launch_bounds__(256, 2) gemm128(
    const float* __restrict__ Aext, long a_off,
    const float* __restrict__ B0, const float* __restrict__ B1,
    const float* __restrict__ B2, const float* __restrict__ B3,
    const float* __restrict__ bias,
    long c_off, int M, int K)
{
    const float* A = Aext ? Aext : (g_f + a_off);
    const float* B = (blockIdx.y == 0) ? B0 : (blockIdx.y == 1) ? B1
                   : (blockIdx.y == 2) ? B2 : B3;
    float* C = g_f + c_off + (long)blockIdx.y * ((long)NN * HID);

    __shared__ float As[2][128 * 20];
    __shared__ float Bs[2][16 * LDBS];

    int tid  = threadIdx.x;
    int warp = tid >> 5, lane = tid & 31;
    int wm = warp >> 1;        // 0..3
    int wn = warp & 1;         // 0..1
    int m_blk = blockIdx.x * 128;

    float c[2][8][4];
#pragma unroll
    for (int i = 0; i < 2; i++)
#pragma unroll
        for (int j = 0; j < 8; j++)
#pragma unroll
            for (int k = 0; k < 4; k++) c[i][j][k] = 0.f;

    int steps = K >> 4;

    // ---- prologue load ----
    {
        int k0 = 0;
#pragma unroll
        for (int c2 = 0; c2 < 2; c2++) {
            int ch = tid + c2 * 256;
            int row = ch >> 2, j = ch & 3;
            bool ok = (m_blk + row) < M;
            long grow = ok ? (long)(m_blk + row) : 0;
            cp16(sptr(&As[0][row * 20 + j * 4]), A + grow * K + k0 + j * 4, ok);
        }
#pragma unroll
        for (int c2 = 0; c2 < 2; c2++) {
            int ch = tid + c2 * 256;
            int row = ch >> 5, j = ch & 31;
            cp16(sptr(&Bs[0][row * LDBS + j * 4]), B + (long)(k0 + row) * 128 + j * 4, true);
        }
        asm volatile("cp.async.commit_group;\n");
    }

    for (int kt = 0; kt < steps; kt++) {
        int b = kt & 1;
        if (kt + 1 < steps) {
            int k0 = (kt + 1) * 16;
            int nb = b ^ 1;
#pragma unroll
            for (int c2 = 0; c2 < 2; c2++) {
                int ch = tid + c2 * 256;
                int row = ch >> 2, j = ch & 3;
                bool ok = (m_blk + row) < M;
                long grow = ok ? (long)(m_blk + row) : 0;
                cp16(sptr(&As[nb][row * 20 + j * 4]), A + grow * K + k0 + j * 4, ok);
            }
#pragma unroll
            for (int c2 = 0; c2 < 2; c2++) {
                int ch = tid + c2 * 256;
                int row = ch >> 5, j = ch & 31;
                cp16(sptr(&Bs[nb][row * LDBS + j * 4]), B + (long)(k0 + row) * 128 + j * 4, true);
            }
            asm volatile("cp.async.commit_group;\n");
            asm volatile("cp.async.wait_group 1;\n");
        } else {
            asm volatile("cp.async.wait_group 0;\n");
        }
        __syncthreads();

        // ---- compute on buffer b ----
#pragma unroll
        for (int ks = 0; ks < 2; ks++) {
            int k0 = ks * 8;
            int kk = k0 + (lane & 3);
            uint32_t ah[2][4], al[2][4];
#pragma unroll
            for (int mi = 0; mi < 2; mi++) {
                int r = wm * 32 + mi * 16 + (lane >> 2);
                float a0 = As[b][r * 20 + kk];
                float a1 = As[b][(r + 8) * 20 + kk];
                float a2 = As[b][r * 20 + kk + 4];
                float a3 = As[b][(r + 8) * 20 + kk + 4];
                split_tf(a0, ah[mi][0], al[mi][0]);
                split_tf(a1, ah[mi][1], al[mi][1]);
                split_tf(a2, ah[mi][2], al[mi][2]);
                split_tf(a3, ah[mi][3], al[mi][3]);
            }
#pragma unroll
            for (int ni = 0; ni < 8; ni++) {
                int col = wn * 64 + ni * 8 + (lane >> 2);
                float b0f = Bs[b][kk * LDBS + col];
                float b1f = Bs[b][(kk + 4) * LDBS + col];
                uint32_t bh[2], bl[2];
                split_tf(b0f, bh[0], bl[0]);
                split_tf(b1f, bh[1], bl[1]);
#pragma unroll
                for (int mi = 0; mi < 2; mi++) {
                    mma8(c[mi][ni], ah[mi], bh);
                    mma8(c[mi][ni], al[mi], bh);
                    mma8(c[mi][ni], ah[mi], bl);
                }
            }
        }
        __syncthreads();
    }

    // ---- epilogue ----
#pragma unroll
    for (int mi = 0; mi < 2; mi++) {
#pragma unroll
        for (int ni = 0; ni < 8; ni++) {
            int col = wn * 64 + ni * 8 + (lane & 3) * 2;
            float bb0 = bias ? bias[col] : 0.f;
            float bb1 = bias ? bias[col + 1] : 0.f;
            int r0 = m_blk + wm * 32 + mi * 16 + (lane >> 2);
            if (r0 < M) {
                float2 v = make_float2(c[mi][ni][0] + bb0, c[mi][ni][1] + bb1);
                *(float2*)(C + (long)r0 * 128 + col) = v;
            }
            int r1 = r0 + 8;
            if (r1 < M) {
                float2 v = make_float2(c[mi][ni][2] + bb0, c[mi][ni][3] + bb1);
                *(float2*)(C + (long)r1 * 128 + col) = v;
            }
        }
    }
}

// ============================================================
// CSR build (stores permuted src + edge weight directly:
// removes the eid -> edge_index dependent load in the GAT loop)
// ============================================================
__global__ void zero_ints(long off, int n) {
    int i = blockIdx.x * blockDim.x + threadIdx.x;
    if (i < n) g_i[off + i] = 0;
}

__global__ void count_deg(const int* __restrict__ ei, int E, long deg_off) {
    int e = blockIdx.x * blockDim.x + threadIdx.x;
    if (e < E) atomicAdd(&g_i[deg_off + ei[E + e]], 1);
}

__global__ void scan_deg(long deg_off, long off_off, long cur_off, int n) {
    __shared__ int ssum[1024];
    int t = threadIdx.x;
    int C = (n + 1023) / 1024;
    int lo = t * C, hi = min(n, (t + 1) * C);
    int s = 0;
    for (int i = lo; i < hi; i++) s += g_i[deg_off + i];
    ssum[t] = s;
    __syncthreads();
    for (int d = 1; d < 1024; d <<= 1) {
        int v = (t >= d) ? ssum[t - d] : 0;
        __syncthreads();
        ssum[t] += v;
        __syncthreads();
    }
    int run = (t == 0) ? 0 : ssum[t - 1];
    for (int i = lo; i < hi; i++) {
        g_i[off_off + i] = run;
        g_i[cur_off + i] = run;
        run += g_i[deg_off + i];
    }
}

__global__ void fill_csr(const int* __restrict__ ei, const float* __restrict__ ew,
                         int E, long cur_off, long src_off, long w_off) {
    int e = blockIdx.x * blockDim.x + threadIdx.x;
    if (e >= E) return;
    int srcv = ei[e];
    int d = ei[E + e];
    int pos = atomicAdd(&g_i[cur_off + d], 1);
    g_i[src_off + pos] = srcv;
    g_f[w_off + pos] = ew[e];
}

// ============================================================
// GATv2, one warp per destination node, ONLINE softmax:
// single gather pass with running (max, sum, acc) per head.
// One-edge-ahead prefetch for memory-level parallelism.
// ============================================================
__global__ void __launch_bounds__(256) gat_kernel(
    long hs_off, long hd_off,
    long off_off, long deg_off, long src_off, long w_off,
    const float* __restrict__ wedge,      // [128]
    const float* __restrict__ attn,       // [4,32]
    const float* __restrict__ bias,       // [128]
    long out_off)
{
    const float* hs   = g_f + hs_off;
    const float* hd   = g_f + hd_off;
    const float* wts  = g_f + w_off;
    const int*   off  = g_i + off_off;
    const int*   degv = g_i + deg_off;
    const int*   srcs = g_i + src_off;
    float* out = g_f + out_off;

    int gw = (blockIdx.x * blockDim.x + threadIdx.x) >> 5;
    if (gw >= NN) return;
    int lane = threadIdx.x & 31;
    int n = gw;
    int begin = off[n];
    int end = begin + degv[n];

    float4 hdv = *(const float4*)(hd + (long)n * 128 + lane * 4);
    float4 wev = *(const float4*)(wedge + lane * 4);
    int h8 = lane >> 3;                          // head this oct handles
    float4 av = *(const float4*)(attn + h8 * 32 + (lane & 7) * 4);

    float m = -1e30f;                            // running max (this head)
    float s = 0.f;                               // running sumexp
    float a0 = 0.f, a1 = 0.f, a2 = 0.f, a3 = 0.f;

    int   sN = 0; float wN = 0.f;
    float4 hN = make_float4(0.f, 0.f, 0.f, 0.f);
    if (begin < end) {
        sN = srcs[begin];
        wN = wts[begin];
        hN = *(const float4*)(hs + (long)sN * 128 + lane * 4);
    }

    for (int p = begin; p < end; p++) {
        float wC = wN;
        float4 hC = hN;
        if (p + 1 < end) {                       // prefetch next edge
            sN = srcs[p + 1];
            wN = wts[p + 1];
            hN = *(const float4*)(hs + (long)sN * 128 + lane * 4);
        }
        float z0 = hC.x + hdv.x + wC * wev.x; z0 = z0 > 0.f ? z0 : 0.2f * z0;
        float z1 = hC.y + hdv.y + wC * wev.y; z1 = z1 > 0.f ? z1 : 0.2f * z1;
        float z2 = hC.z + hdv.z + wC * wev.z; z2 = z2 > 0.f ? z2 : 0.2f * z2;
        float z3 = hC.w + hdv.w + wC * wev.w; z3 = z3 > 0.f ? z3 : 0.2f * z3;
        float part = av.x * z0 + av.y * z1 + av.z * z2 + av.w * z3;
        // butterfly within oct -> every lane of the oct holds its head's logit
        part += __shfl_xor_sync(0xffffffffu, part, 4);
        part += __shfl_xor_sync(0xffffffffu, part, 2);
        part += __shfl_xor_sync(0xffffffffu, part, 1);

        float mn   = fmaxf(m, part);
        float corr = __expf(m - mn);
        float pr   = __expf(part - mn);
        s  = s * corr + pr;
        a0 = a0 * corr + pr * hC.x;
        a1 = a1 * corr + pr * hC.y;
        a2 = a2 * corr + pr * hC.z;
        a3 = a3 * corr + pr * hC.w;
        m = mn;
    }

    float inv = 1.f / (s + 1e-16f);
    float4 o = make_float4(a0 * inv + bias[lane * 4],
                           a1 * inv + bias[lane * 4 + 1],
                           a2 * inv + bias[lane * 4 + 2],
                           a3 * inv + bias[lane * 4 + 3]);
    *(float4*)(out + (long)n * 128 + lane * 4) = o;
}

// ============================================================
// combine + ELU + LayerNorm: one warp per row
// ============================================================
__global__ void __launch_bounds__(256) combine_ln(
    const float* __restrict__ alpha,
    const float* __restrict__ ln_scale,
    const float* __restrict__ ln_bias,
    float* __restrict__ out)
{
    int gw = (blockIdx.x * blockDim.x + threadIdx.x) >> 5;
    if (gw >= NN) return;
    int lane = threadIdx.x & 31;
    float a = *alpha;
    const float* hf = g_f + F_OUTF + (long)gw * 128;
    const float* hp = g_f + F_OUTP + (long)gw * 128;

    float x[4];
#pragma unroll
    for (int i = 0; i < 4; i++) {
        float v = (1.f - a) * hf[lane * 4 + i] + a * hp[lane * 4 + i];
        x[i] = v > 0.f ? v : expm1f(v);
    }
    float s = x[0] + x[1] + x[2] + x[3];
#pragma unroll
    for (int o = 16; o > 0; o >>= 1) s += __shfl_xor_sync(0xffffffffu, s, o);
    float mu = s * (1.f / 128.f);
    float vs = 0.f;
#pragma unroll
    for (int i = 0; i < 4; i++) { float d = x[i] - mu; vs += d * d; }
#pragma unroll
    for (int o = 16; o > 0; o >>= 1) vs += __shfl_xor_sync(0xffffffffu, vs, o);
    float r = rsqrtf(vs * (1.f / 128.f) + 1e-6f);
#pragma unroll
    for (int i = 0; i < 4; i++) {
        int col = lane * 4 + i;
        out[(long)gw * 128 + col] = (x[i] - mu) * r * ln_scale[col] + ln_bias[col];
    }
}

// ============================================================
extern "C" void kernel_launch(void* const* d_in, const int* in_sizes, int n_in,
                              void* d_out, int out_size) {
    const float* X       = (const float*)d_in[0];
    const int*   eif     = (const int*)  d_in[1];
    const float* ewf     = (const float*)d_in[2];
    const int*   eip     = (const int*)  d_in[3];
    const float* ewp     = (const float*)d_in[4];
    const float* alpha   = (const float*)d_in[5];
    const float* ip_w    = (const float*)d_in[6];
    const float* ip_b    = (const float*)d_in[7];
    const float* gf_wsrc = (const float*)d_in[8];
    const float* gf_wdst = (const float*)d_in[9];
    const float* gf_wedge= (const float*)d_in[10];
    const float* gf_attn = (const float*)d_in[11];
    const float* gf_bias = (const float*)d_in[12];
    const float* gp_wsrc = (const float*)d_in[13];
    const float* gp_wdst = (const float*)d_in[14];
    const float* gp_wedge= (const float*)d_in[15];
    const float* gp_attn = (const float*)d_in[16];
    const float* gp_bias = (const float*)d_in[17];
    const float* ln_scale= (const float*)d_in[18];
    const float* ln_bias = (const float*)d_in[19];
    float* out = (float*)d_out;

    int gm = (NN + 127) / 128;   // 391

    // CSR build first (independent of GEMMs; lets it overlap launch tails)
    int gz = (NN + 255) / 256;
    zero_ints<<<gz, 256>>>(I_DEGF, NN);
    zero_ints<<<gz, 256>>>(I_DEGP, NN);
    count_deg<<<(EF + 255) / 256, 256>>>(eif, EF, I_DEGF);
    count_deg<<<(EP + 255) / 256, 256>>>(eip, EP, I_DEGP);
    scan_deg<<<1, 1024>>>(I_DEGF, I_OFFF, I_CURF, NN);
    scan_deg<<<1, 1024>>>(I_DEGP, I_OFFP, I_CURP, NN);
    fill_csr<<<(EF + 255) / 256, 256>>>(eif, ewf, EF, I_CURF, I_SRCF, F_WF);
    fill_csr<<<(EP + 255) / 256, 256>>>(eip, ewp, EP, I_CURP, I_SRCP, F_WP);

    // input projection (grid.y = 1)
    dim3 g1(gm, 1);
    gemm128<<<g1, 256>>>(X, 0, ip_w, ip_w, ip_w, ip_w, ip_b, F_H, NN, 2000);

    // all 4 h-projections in ONE batched launch (grid.y = 4);
    // outputs land in the contiguous HSF/HDF/HSP/HDP scratch blocks
    dim3 g4(gm, 4);
    gemm128<<<g4, 256>>>(nullptr, F_H, gf_wsrc, gf_wdst, gp_wsrc, gp_wdst,
                         nullptr, F_HSF, NN, 128);

    // GATv2 (online softmax) on both graphs
    int gg = (NN * 32 + 255) / 256;
    gat_kernel<<<gg, 256>>>(F_HSF, F_HDF, I_OFFF, I_DEGF, I_SRCF, F_WF,
                            gf_wedge, gf_attn, gf_bias, F_OUTF);
    gat_kernel<<<gg, 256>>>(F_HSP, F_HDP, I_OFFP, I_DEGP, I_SRCP, F_WP,
                            gp_wedge, gp_attn, gp_bias, F_OUTP);

    // combine + elu + layernorm
    combine_ln<<<gg, 256>>>(alpha, ln_scale, ln_bias, out);
}

// round 16
// speedup vs baseline: 1.6717x; 1.5582x over previous
#include <cuda_runtime.h>
#include <cuda_bf16.h>
#include <cstdint>
#include <math.h>

#define NN   50000
#define HID  128
#define EF   800000
#define EP   400000

// ---------------- float scratch layout ----------------
constexpr long F_H    = 0;
constexpr long F_HSF  = F_H    + (long)NN * HID;
constexpr long F_HDF  = F_HSF  + (long)NN * HID;   // HSF,HDF,HSP,HDP contiguous:
constexpr long F_HSP  = F_HDF  + (long)NN * HID;   // batched GEMM writes via
constexpr long F_HDP  = F_HSP  + (long)NN * HID;   // blockIdx.y
constexpr long F_OUTF = F_HDP  + (long)NN * HID;
constexpr long F_OUTP = F_OUTF + (long)NN * HID;
constexpr long F_WF   = F_OUTP + (long)NN * HID;   // permuted edge weights
constexpr long F_WP   = F_WF   + (long)EF;
constexpr long F_TOT  = F_WP   + (long)EP;

// ---------------- int scratch layout -------------------
constexpr long I_DEGF = 0;
constexpr long I_OFFF = I_DEGF + NN;
constexpr long I_CURF = I_OFFF + NN;
constexpr long I_DEGP = I_CURF + NN;
constexpr long I_OFFP = I_DEGP + NN;
constexpr long I_CURP = I_OFFP + NN;
constexpr long I_SRCF = I_CURP + NN;               // permuted src ids
constexpr long I_SRCP = I_SRCF + (long)EF;
constexpr long I_TOT  = I_SRCP + (long)EP;

// ---------------- bf16 weight scratch (hi/lo split, tiled) ----
// layout per matrix: [k16-chunk][n(128)][kk(16)]
constexpr long B_IP   = 0;                          // 2000*128
constexpr long B_GF_S = B_IP   + 2000L * 128;
constexpr long B_GF_D = B_GF_S + 128L * 128;
constexpr long B_GP_S = B_GF_D + 128L * 128;
constexpr long B_GP_D = B_GP_S + 128L * 128;
constexpr long B_TOT  = B_GP_D + 128L * 128;

__device__ float          g_f[F_TOT];
__device__ int            g_i[I_TOT];
__device__ __nv_bfloat16  g_bh[B_TOT];
__device__ __nv_bfloat16  g_bl[B_TOT];

// ---------------- helpers ----------------
__device__ __forceinline__ void split2(float x, float y, uint32_t& hi, uint32_t& lo) {
    __nv_bfloat162 h = __floats2bfloat162_rn(x, y);
    float rx = x - __bfloat162float(h.x);
    float ry = y - __bfloat162float(h.y);
    __nv_bfloat162 l = __floats2bfloat162_rn(rx, ry);
    hi = *(uint32_t*)&h;
    lo = *(uint32_t*)&l;
}

__device__ __forceinline__ void mma16(float* c, const uint32_t* a, const uint32_t* b) {
    asm volatile(
        "mma.sync.aligned.m16n8k16.row.col.f32.bf16.bf16.f32 "
        "{%0,%1,%2,%3}, {%4,%5,%6,%7}, {%8,%9}, {%0,%1,%2,%3};\n"
        : "+f"(c[0]), "+f"(c[1]), "+f"(c[2]), "+f"(c[3])
        : "r"(a[0]), "r"(a[1]), "r"(a[2]), "r"(a[3]),
          "r"(b[0]), "r"(b[1]));
}

__device__ __forceinline__ void cp16(uint32_t dst, const void* src, bool p) {
    int sz = p ? 16 : 0;
    asm volatile("cp.async.ca.shared.global [%0], [%1], 16, %2;\n"
                 :: "r"(dst), "l"(src), "r"(sz));
}

__device__ __forceinline__ uint32_t sptr(const void* p) {
    return (uint32_t)__cvta_generic_to_shared(p);
}

// ============================================================
// Pre-convert the 5 weight matrices to bf16 hi/lo, tiled layout
// [k16][n][kk] so GEMM cp.asyncs them straight into fragments.
// ============================================================
__global__ void convB(const float* __restrict__ ip,
                      const float* __restrict__ b1, const float* __restrict__ b2,
                      const float* __restrict__ b3, const float* __restrict__ b4) {
    int idx = blockIdx.x * blockDim.x + threadIdx.x;
    const float* src;
    long dst;
    int local;
    if (idx < 2000 * 128) {
        src = ip; dst = B_IP; local = idx;
    } else {
        int r = idx - 2000 * 128;
        if (r >= 4 * 128 * 128) return;
        int t = r >> 14;              // which 128x128 matrix
        local = r & 16383;
        src = (t == 0) ? b1 : (t == 1) ? b2 : (t == 2) ? b3 : b4;
        dst = B_GF_S + (long)t * 16384;
    }
    int k = local >> 7, n = local & 127;
    float w = src[local];
    __nv_bfloat16 h = __float2bfloat16(w);
    __nv_bfloat16 l = __float2bfloat16(w - __bfloat162float(h));
    long pos = dst + ((long)(k >> 4) * 128 + n) * 16 + (k & 15);
    g_bh[pos] = h;
    g_bl[pos] = l;
}

// ============================================================
// GEMM: C[M,128] = A[M,K] @ Bsel[K,128] (+bias), bf16-split-3
// CTA = 128x128 tile, 8 warps of 32x64, double-buffered cp.async.
// gridDim.y selects among 4 pre-converted B matrices.
// As: fp32 [128][20] ; Bsh/Bsl: bf16 [128 n][24] (conflict-free)
// ============================================================
#define LDA 20
#define LDB 24

__global__ void __launch_bounds__(256, 2) gemm128(
    const float* __restrict__ Aext, long a_off,
    long bo0, long bo1, long bo2, long bo3,
    const float* __restrict__ bias,
    long c_off, int M, int K)
{
    const float* A = Aext ? Aext : (g_f + a_off);
    long bo = (blockIdx.y == 0) ? bo0 : (blockIdx.y == 1) ? bo1
            : (blockIdx.y == 2) ? bo2 : bo3;
    const __nv_bfloat16* Bh = g_bh + bo;
    const __nv_bfloat16* Bl = g_bl + bo;
    float* C = g_f + c_off + (long)blockIdx.y * ((long)NN * HID);

    __shared__ float         As[2][128 * LDA];
    __shared__ __nv_bfloat16 Bsh[2][128 * LDB];
    __shared__ __nv_bfloat16 Bsl[2][128 * LDB];

    int tid  = threadIdx.x;
    int warp = tid >> 5, lane = tid & 31;
    int wm = warp >> 1;        // 0..3
    int wn = warp & 1;         // 0..1
    int m_blk = blockIdx.x * 128;

    float c[2][8][4];
#pragma unroll
    for (int i = 0; i < 2; i++)
#pragma unroll
        for (int j = 0; j < 8; j++)
#pragma unroll
            for (int k = 0; k < 4; k++) c[i][j][k] = 0.f;

    int steps = K >> 4;

    // per-thread load coords
    int a_row = tid >> 2, a_j = tid & 3;           // + second chunk at +256
    int b_n = tid >> 1, b_h = tid & 1;

    // ---- prologue ----
    {
#pragma unroll
        for (int c2 = 0; c2 < 2; c2++) {
            int row = a_row + c2 * 64;
            bool ok = (m_blk + row) < M;
            long grow = ok ? (long)(m_blk + row) : 0;
            cp16(sptr(&As[0][row * LDA + a_j * 4]), A + grow * K + a_j * 4, ok);
        }
        cp16(sptr(&Bsh[0][b_n * LDB + b_h * 8]), Bh + (long)b_n * 16 + b_h * 8, true);
        cp16(sptr(&Bsl[0][b_n * LDB + b_h * 8]), Bl + (long)b_n * 16 + b_h * 8, true);
        asm volatile("cp.async.commit_group;\n");
    }

    int r0 = wm * 32 + (lane >> 2);
    int ka = (lane & 3) * 2;

    for (int kt = 0; kt < steps; kt++) {
        int b = kt & 1;
        if (kt + 1 < steps) {
            int k0 = (kt + 1) * 16;
            int nb = b ^ 1;
            long bbase = (long)(kt + 1) * 2048;
#pragma unroll
            for (int c2 = 0; c2 < 2; c2++) {
                int row = a_row + c2 * 64;
                bool ok = (m_blk + row) < M;
                long grow = ok ? (long)(m_blk + row) : 0;
                cp16(sptr(&As[nb][row * LDA + a_j * 4]), A + grow * K + k0 + a_j * 4, ok);
            }
            cp16(sptr(&Bsh[nb][b_n * LDB + b_h * 8]), Bh + bbase + (long)b_n * 16 + b_h * 8, true);
            cp16(sptr(&Bsl[nb][b_n * LDB + b_h * 8]), Bl + bbase + (long)b_n * 16 + b_h * 8, true);
            asm volatile("cp.async.commit_group;\n");
            asm volatile("cp.async.wait_group 1;\n");
        } else {
            asm volatile("cp.async.wait_group 0;\n");
        }
        __syncthreads();

        // ---- A fragments: fp32 -> bf16 hi/lo ----
        uint32_t ah[2][4], al[2][4];
#pragma unroll
        for (int mi = 0; mi < 2; mi++) {
            int r = r0 + mi * 16;
            float2 p0 = *(const float2*)&As[b][r * LDA + ka];
            float2 p1 = *(const float2*)&As[b][(r + 8) * LDA + ka];
            float2 p2 = *(const float2*)&As[b][r * LDA + ka + 8];
            float2 p3 = *(const float2*)&As[b][(r + 8) * LDA + ka + 8];
            split2(p0.x, p0.y, ah[mi][0], al[mi][0]);
            split2(p1.x, p1.y, ah[mi][1], al[mi][1]);
            split2(p2.x, p2.y, ah[mi][2], al[mi][2]);
            split2(p3.x, p3.y, ah[mi][3], al[mi][3]);
        }

        // ---- B fragments straight from bf16 smem + 3-term MMA ----
#pragma unroll
        for (int ni = 0; ni < 8; ni++) {
            int col = wn * 64 + ni * 8 + (lane >> 2);
            uint32_t bh[2], bl[2];
            bh[0] = *(const uint32_t*)&Bsh[b][col * LDB + ka];
            bh[1] = *(const uint32_t*)&Bsh[b][col * LDB + ka + 8];
            bl[0] = *(const uint32_t*)&Bsl[b][col * LDB + ka];
            bl[1] = *(const uint32_t*)&Bsl[b][col * LDB + ka + 8];
#pragma unroll
            for (int mi = 0; mi < 2; mi++) {
                mma16(c[mi][ni], ah[mi], bh);
                mma16(c[mi][ni], al[mi], bh);
                mma16(c[mi][ni], ah[mi], bl);
            }
        }
        __syncthreads();
    }

    // ---- epilogue ----
#pragma unroll
    for (int mi = 0; mi < 2; mi++) {
#pragma unroll
        for (int ni = 0; ni < 8; ni++) {
            int col = wn * 64 + ni * 8 + (lane & 3) * 2;
            float bb0 = bias ? bias[col] : 0.f;
            float bb1 = bias ? bias[col + 1] : 0.f;
            int r = m_blk + wm * 32 + mi * 16 + (lane >> 2);
            if (r < M) {
                float2 v = make_float2(c[mi][ni][0] + bb0, c[mi][ni][1] + bb1);
                *(float2*)(C + (long)r * 128 + col) = v;
            }
            if (r + 8 < M) {
                float2 v = make_float2(c[mi][ni][2] + bb0, c[mi][ni][3] + bb1);
                *(float2*)(C + (long)(r + 8) * 128 + col) = v;
            }
        }
    }
}

// ============================================================
// CSR build (both graphs per launch)
// ============================================================
__global__ void zero2() {
    int i = blockIdx.x * blockDim.x + threadIdx.x;
    if (i < NN) g_i[I_DEGF + i] = 0;
    else if (i < 2 * NN) g_i[I_DEGP + i - NN] = 0;
}

__global__ void count_deg2(const int* __restrict__ eif, const int* __restrict__ eip) {
    int e = blockIdx.x * blockDim.x + threadIdx.x;
    if (e < EF) {
        atomicAdd(&g_i[I_DEGF + eif[EF + e]], 1);
    } else {
        int e2 = e - EF;
        if (e2 < EP) atomicAdd(&g_i[I_DEGP + eip[EP + e2]], 1);
    }
}

__global__ void scan_deg2() {
    long deg_off = blockIdx.x ? I_DEGP : I_DEGF;
    long off_off = blockIdx.x ? I_OFFP : I_OFFF;
    long cur_off = blockIdx.x ? I_CURP : I_CURF;
    __shared__ int ssum[1024];
    int t = threadIdx.x;
    const int C = (NN + 1023) / 1024;
    int lo = t * C, hi = min(NN, (t + 1) * C);
    int s = 0;
    for (int i = lo; i < hi; i++) s += g_i[deg_off + i];
    ssum[t] = s;
    __syncthreads();
    for (int d = 1; d < 1024; d <<= 1) {
        int v = (t >= d) ? ssum[t - d] : 0;
        __syncthreads();
        ssum[t] += v;
        __syncthreads();
    }
    int run = (t == 0) ? 0 : ssum[t - 1];
    for (int i = lo; i < hi; i++) {
        g_i[off_off + i] = run;
        g_i[cur_off + i] = run;
        run += g_i[deg_off + i];
    }
}

__global__ void fill_csr2(const int* __restrict__ eif, const float* __restrict__ ewf,
                          const int* __restrict__ eip, const float* __restrict__ ewp) {
    int e = blockIdx.x * blockDim.x + threadIdx.x;
    if (e < EF) {
        int srcv = eif[e];
        int d = eif[EF + e];
        int pos = atomicAdd(&g_i[I_CURF + d], 1);
        g_i[I_SRCF + pos] = srcv;
        g_f[F_WF + pos] = ewf[e];
    } else {
        int e2 = e - EF;
        if (e2 >= EP) return;
        int srcv = eip[e2];
        int d = eip[EP + e2];
        int pos = atomicAdd(&g_i[I_CURP + d], 1);
        g_i[I_SRCP + pos] = srcv;
        g_f[F_WP + pos] = ewp[e2];
    }
}

// ============================================================
// GATv2, one warp per destination node, online softmax.
// ============================================================
__global__ void __launch_bounds__(256) gat_kernel(
    long hs_off, long hd_off,
    long off_off, long deg_off, long src_off, long w_off,
    const float* __restrict__ wedge,      // [128]
    const float* __restrict__ attn,       // [4,32]
    const float* __restrict__ bias,       // [128]
    long out_off)
{
    const float* hs   = g_f + hs_off;
    const float* hd   = g_f + hd_off;
    const float* wts  = g_f + w_off;
    const int*   off  = g_i + off_off;
    const int*   degv = g_i + deg_off;
    const int*   srcs = g_i + src_off;
    float* out = g_f + out_off;

    int gw = (blockIdx.x * blockDim.x + threadIdx.x) >> 5;
    if (gw >= NN) return;
    int lane = threadIdx.x & 31;
    int n = gw;
    int begin = off[n];
    int end = begin + degv[n];

    float4 hdv = *(const float4*)(hd + (long)n * 128 + lane * 4);
    float4 wev = *(const float4*)(wedge + lane * 4);
    int h8 = lane >> 3;
    float4 av = *(const float4*)(attn + h8 * 32 + (lane & 7) * 4);

    float m = -1e30f;
    float s = 0.f;
    float a0 = 0.f, a1 = 0.f, a2 = 0.f, a3 = 0.f;

    int   sN = 0; float wN = 0.f;
    float4 hN = make_float4(0.f, 0.f, 0.f, 0.f);
    if (begin < end) {
        sN = srcs[begin];
        wN = wts[begin];
        hN = *(const float4*)(hs + (long)sN * 128 + lane * 4);
    }

    for (int p = begin; p < end; p++) {
        float wC = wN;
        float4 hC = hN;
        if (p + 1 < end) {
            sN = srcs[p + 1];
            wN = wts[p + 1];
            hN = *(const float4*)(hs + (long)sN * 128 + lane * 4);
        }
        float z0 = hC.x + hdv.x + wC * wev.x; z0 = z0 > 0.f ? z0 : 0.2f * z0;
        float z1 = hC.y + hdv.y + wC * wev.y; z1 = z1 > 0.f ? z1 : 0.2f * z1;
        float z2 = hC.z + hdv.z + wC * wev.z; z2 = z2 > 0.f ? z2 : 0.2f * z2;
        float z3 = hC.w + hdv.w + wC * wev.w; z3 = z3 > 0.f ? z3 : 0.2f * z3;
        float part = av.x * z0 + av.y * z1 + av.z * z2 + av.w * z3;
        part += __shfl_xor_sync(0xffffffffu, part, 4);
        part += __shfl_xor_sync(0xffffffffu, part, 2);
        part += __shfl_xor_sync(0xffffffffu, part, 1);

        float mn   = fmaxf(m, part);
        float corr = __expf(m - mn);
        float pr   = __expf(part - mn);
        s  = s * corr + pr;
        a0 = a0 * corr + pr * hC.x;
        a1 = a1 * corr + pr * hC.y;
        a2 = a2 * corr + pr * hC.z;
        a3 = a3 * corr + pr * hC.w;
        m = mn;
    }

    float inv = 1.f / (s + 1e-16f);
    float4 o = make_float4(a0 * inv + bias[lane * 4],
                           a1 * inv + bias[lane * 4 + 1],
                           a2 * inv + bias[lane * 4 + 2],
                           a3 * inv + bias[lane * 4 + 3]);
    *(float4*)(out + (long)n * 128 + lane * 4) = o;
}

// ============================================================
// combine + ELU + LayerNorm: one warp per row
// ============================================================
__global__ void __launch_bounds__(256) combine_ln(
    const float* __restrict__ alpha,
    const float* __restrict__ ln_scale,
    const float* __restrict__ ln_bias,
    float* __restrict__ out)
{
    int gw = (blockIdx.x * blockDim.x + threadIdx.x) >> 5;
    if (gw >= NN) return;
    int lane = threadIdx.x & 31;
    float a = *alpha;
    const float* hf = g_f + F_OUTF + (long)gw * 128;
    const float* hp = g_f + F_OUTP + (long)gw * 128;

    float x[4];
#pragma unroll
    for (int i = 0; i < 4; i++) {
        float v = (1.f - a) * hf[lane * 4 + i] + a * hp[lane * 4 + i];
        x[i] = v > 0.f ? v : expm1f(v);
    }
    float s = x[0] + x[1] + x[2] + x[3];
#pragma unroll
    for (int o = 16; o > 0; o >>= 1) s += __shfl_xor_sync(0xffffffffu, s, o);
    float mu = s * (1.f / 128.f);
    float vs = 0.f;
#pragma unroll
    for (int i = 0; i < 4; i++) { float d = x[i] - mu; vs += d * d; }
#pragma unroll
    for (int o = 16; o > 0; o >>= 1) vs += __shfl_xor_sync(0xffffffffu, vs, o);
    float r = rsqrtf(vs * (1.f / 128.f) + 1e-6f);
#pragma unroll
    for (int i = 0; i < 4; i++) {
        int col = lane * 4 + i;
        out[(long)gw * 128 + col] = (x[i] - mu) * r * ln_scale[col] + ln_bias[col];
    }
}

// ============================================================
extern "C" void kernel_launch(void* const* d_in, const int* in_sizes, int n_in,
                              void* d_out, int out_size) {
    const float* X       = (const float*)d_in[0];
    const int*   eif     = (const int*)  d_in[1];
    const float* ewf     = (const float*)d_in[2];
    const int*   eip     = (const int*)  d_in[3];
    const float* ewp     = (const float*)d_in[4];
    const float* alpha   = (const float*)d_in[5];
    const float* ip_w    = (const float*)d_in[6];
    const float* ip_b    = (const float*)d_in[7];
    const float* gf_wsrc = (const float*)d_in[8];
    const float* gf_wdst = (const float*)d_in[9];
    const float* gf_wedge= (const float*)d_in[10];
    const float* gf_attn = (const float*)d_in[11];
    const float* gf_bias = (const float*)d_in[12];
    const float* gp_wsrc = (const float*)d_in[13];
    const float* gp_wdst = (const float*)d_in[14];
    const float* gp_wedge= (const float*)d_in[15];
    const float* gp_attn = (const float*)d_in[16];
    const float* gp_bias = (const float*)d_in[17];
    const float* ln_scale= (const float*)d_in[18];
    const float* ln_bias = (const float*)d_in[19];
    float* out = (float*)d_out;

    int gm = (NN + 127) / 128;   // 391

    // weight pre-conversion to bf16 hi/lo tiled layout
    int convN = 2000 * 128 + 4 * 128 * 128;
    convB<<<(convN + 255) / 256, 256>>>(ip_w, gf_wsrc, gf_wdst, gp_wsrc, gp_wdst);

    // CSR build (merged launches, both graphs each)
    zero2<<<(2 * NN + 255) / 256, 256>>>();
    count_deg2<<<(EF + EP + 255) / 256, 256>>>(eif, eip);
    scan_deg2<<<2, 1024>>>();
    fill_csr2<<<(EF + EP + 255) / 256, 256>>>(eif, ewf, eip, ewp);

    // input projection (grid.y = 1)
    dim3 g1(gm, 1);
    gemm128<<<g1, 256>>>(X, 0, B_IP, B_IP, B_IP, B_IP, ip_b, F_H, NN, 2000);

    // all 4 h-projections in ONE batched launch (grid.y = 4)
    dim3 g4(gm, 4);
    gemm128<<<g4, 256>>>(nullptr, F_H, B_GF_S, B_GF_D, B_GP_S, B_GP_D,
                         nullptr, F_HSF, NN, 128);

    // GATv2 (online softmax) on both graphs
    int gg = (NN * 32 + 255) / 256;
    gat_kernel<<<gg, 256>>>(F_HSF, F_HDF, I_OFFF, I_DEGF, I_SRCF, F_WF,
                            gf_wedge, gf_attn, gf_bias, F_OUTF);
    gat_kernel<<<gg, 256>>>(F_HSP, F_HDP, I_OFFP, I_DEGP, I_SRCP, F_WP,
                            gp_wedge, gp_attn, gp_bias, F_OUTP);

    // combine + elu + layernorm
    combine_ln<<<gg, 256>>>(alpha, ln_scale, ln_bias, out);
}

// round 17
// speedup vs baseline: 1.8787x; 1.1238x over previous
#include <cuda_runtime.h>
#include <cuda_bf16.h>
#include <cstdint>
#include <math.h>

#define NN   50000
#define HID  128
#define EF   800000
#define EP   400000
#define NB   ((NN + 1023) / 1024)   // 49 scan blocks per graph

// ---------------- float scratch layout ----------------
constexpr long F_H    = 0;
constexpr long F_HSF  = F_H    + (long)NN * HID;
constexpr long F_HDF  = F_HSF  + (long)NN * HID;   // HSF,HDF,HSP,HDP contiguous:
constexpr long F_HSP  = F_HDF  + (long)NN * HID;   // batched GEMM writes via
constexpr long F_HDP  = F_HSP  + (long)NN * HID;   // blockIdx.y
constexpr long F_OUTF = F_HDP  + (long)NN * HID;
constexpr long F_OUTP = F_OUTF + (long)NN * HID;
constexpr long F_WF   = F_OUTP + (long)NN * HID;   // permuted edge weights
constexpr long F_WP   = F_WF   + (long)EF;
constexpr long F_TOT  = F_WP   + (long)EP;

// ---------------- int scratch layout -------------------
constexpr long I_DEGF = 0;
constexpr long I_OFFF = I_DEGF + NN;
constexpr long I_CURF = I_OFFF + NN;
constexpr long I_DEGP = I_CURF + NN;
constexpr long I_OFFP = I_DEGP + NN;
constexpr long I_CURP = I_OFFP + NN;
constexpr long I_BSF  = I_CURP + NN;               // per-block scan sums
constexpr long I_BSP  = I_BSF  + NB;
constexpr long I_SRCF = I_BSP  + NB;               // permuted src ids
constexpr long I_SRCP = I_SRCF + (long)EF;
constexpr long I_TOT  = I_SRCP + (long)EP;

// ---------------- bf16 weight scratch (hi/lo split, tiled) ----
// layout per matrix: [k16-chunk][n(128)][kk(16)]
constexpr long B_IP   = 0;                          // 2000*128
constexpr long B_GF_S = B_IP   + 2000L * 128;
constexpr long B_GF_D = B_GF_S + 128L * 128;
constexpr long B_GP_S = B_GF_D + 128L * 128;
constexpr long B_GP_D = B_GP_S + 128L * 128;
constexpr long B_TOT  = B_GP_D + 128L * 128;

__device__ float          g_f[F_TOT];
__device__ int            g_i[I_TOT];
__device__ __nv_bfloat16  g_bh[B_TOT];
__device__ __nv_bfloat16  g_bl[B_TOT];

// ---------------- helpers ----------------
__device__ __forceinline__ void split2(float x, float y, uint32_t& hi, uint32_t& lo) {
    __nv_bfloat162 h = __floats2bfloat162_rn(x, y);
    float rx = x - __bfloat162float(h.x);
    float ry = y - __bfloat162float(h.y);
    __nv_bfloat162 l = __floats2bfloat162_rn(rx, ry);
    hi = *(uint32_t*)&h;
    lo = *(uint32_t*)&l;
}

__device__ __forceinline__ void mma16(float* c, const uint32_t* a, const uint32_t* b) {
    asm volatile(
        "mma.sync.aligned.m16n8k16.row.col.f32.bf16.bf16.f32 "
        "{%0,%1,%2,%3}, {%4,%5,%6,%7}, {%8,%9}, {%0,%1,%2,%3};\n"
        : "+f"(c[0]), "+f"(c[1]), "+f"(c[2]), "+f"(c[3])
        : "r"(a[0]), "r"(a[1]), "r"(a[2]), "r"(a[3]),
          "r"(b[0]), "r"(b[1]));
}

__device__ __forceinline__ void cp16(uint32_t dst, const void* src, bool p) {
    int sz = p ? 16 : 0;
    asm volatile("cp.async.ca.shared.global [%0], [%1], 16, %2;\n"
                 :: "r"(dst), "l"(src), "r"(sz));
}

__device__ __forceinline__ uint32_t sptr(const void* p) {
    return (uint32_t)__cvta_generic_to_shared(p);
}

// ============================================================
// Pre-convert the 5 weight matrices to bf16 hi/lo, tiled layout
// ============================================================
__global__ void convB(const float* __restrict__ ip,
                      const float* __restrict__ b1, const float* __restrict__ b2,
                      const float* __restrict__ b3, const float* __restrict__ b4) {
    int idx = blockIdx.x * blockDim.x + threadIdx.x;
    const float* src;
    long dst;
    int local;
    if (idx < 2000 * 128) {
        src = ip; dst = B_IP; local = idx;
    } else {
        int r = idx - 2000 * 128;
        if (r >= 4 * 128 * 128) return;
        int t = r >> 14;              // which 128x128 matrix
        local = r & 16383;
        src = (t == 0) ? b1 : (t == 1) ? b2 : (t == 2) ? b3 : b4;
        dst = B_GF_S + (long)t * 16384;
    }
    int k = local >> 7, n = local & 127;
    float w = src[local];
    __nv_bfloat16 h = __float2bfloat16(w);
    __nv_bfloat16 l = __float2bfloat16(w - __bfloat162float(h));
    long pos = dst + ((long)(k >> 4) * 128 + n) * 16 + (k & 15);
    g_bh[pos] = h;
    g_bl[pos] = l;
}

// ============================================================
// GEMM: C[M,128] = A[M,K] @ Bsel[K,128] (+bias), bf16-split-3
// ============================================================
#define LDA 20
#define LDB 24

__global__ void __launch_bounds__(256, 2) gemm128(
    const float* __restrict__ Aext, long a_off,
    long bo0, long bo1, long bo2, long bo3,
    const float* __restrict__ bias,
    long c_off, int M, int K)
{
    const float* A = Aext ? Aext : (g_f + a_off);
    long bo = (blockIdx.y == 0) ? bo0 : (blockIdx.y == 1) ? bo1
            : (blockIdx.y == 2) ? bo2 : bo3;
    const __nv_bfloat16* Bh = g_bh + bo;
    const __nv_bfloat16* Bl = g_bl + bo;
    float* C = g_f + c_off + (long)blockIdx.y * ((long)NN * HID);

    __shared__ float         As[2][128 * LDA];
    __shared__ __nv_bfloat16 Bsh[2][128 * LDB];
    __shared__ __nv_bfloat16 Bsl[2][128 * LDB];

    int tid  = threadIdx.x;
    int warp = tid >> 5, lane = tid & 31;
    int wm = warp >> 1;        // 0..3
    int wn = warp & 1;         // 0..1
    int m_blk = blockIdx.x * 128;

    float c[2][8][4];
#pragma unroll
    for (int i = 0; i < 2; i++)
#pragma unroll
        for (int j = 0; j < 8; j++)
#pragma unroll
            for (int k = 0; k < 4; k++) c[i][j][k] = 0.f;

    int steps = K >> 4;

    int a_row = tid >> 2, a_j = tid & 3;
    int b_n = tid >> 1, b_h = tid & 1;

    // ---- prologue ----
    {
#pragma unroll
        for (int c2 = 0; c2 < 2; c2++) {
            int row = a_row + c2 * 64;
            bool ok = (m_blk + row) < M;
            long grow = ok ? (long)(m_blk + row) : 0;
            cp16(sptr(&As[0][row * LDA + a_j * 4]), A + grow * K + a_j * 4, ok);
        }
        cp16(sptr(&Bsh[0][b_n * LDB + b_h * 8]), Bh + (long)b_n * 16 + b_h * 8, true);
        cp16(sptr(&Bsl[0][b_n * LDB + b_h * 8]), Bl + (long)b_n * 16 + b_h * 8, true);
        asm volatile("cp.async.commit_group;\n");
    }

    int r0 = wm * 32 + (lane >> 2);
    int ka = (lane & 3) * 2;

    for (int kt = 0; kt < steps; kt++) {
        int b = kt & 1;
        if (kt + 1 < steps) {
            int k0 = (kt + 1) * 16;
            int nb = b ^ 1;
            long bbase = (long)(kt + 1) * 2048;
#pragma unroll
            for (int c2 = 0; c2 < 2; c2++) {
                int row = a_row + c2 * 64;
                bool ok = (m_blk + row) < M;
                long grow = ok ? (long)(m_blk + row) : 0;
                cp16(sptr(&As[nb][row * LDA + a_j * 4]), A + grow * K + k0 + a_j * 4, ok);
            }
            cp16(sptr(&Bsh[nb][b_n * LDB + b_h * 8]), Bh + bbase + (long)b_n * 16 + b_h * 8, true);
            cp16(sptr(&Bsl[nb][b_n * LDB + b_h * 8]), Bl + bbase + (long)b_n * 16 + b_h * 8, true);
            asm volatile("cp.async.commit_group;\n");
            asm volatile("cp.async.wait_group 1;\n");
        } else {
            asm volatile("cp.async.wait_group 0;\n");
        }
        __syncthreads();

        uint32_t ah[2][4], al[2][4];
#pragma unroll
        for (int mi = 0; mi < 2; mi++) {
            int r = r0 + mi * 16;
            float2 p0 = *(const float2*)&As[b][r * LDA + ka];
            float2 p1 = *(const float2*)&As[b][(r + 8) * LDA + ka];
            float2 p2 = *(const float2*)&As[b][r * LDA + ka + 8];
            float2 p3 = *(const float2*)&As[b][(r + 8) * LDA + ka + 8];
            split2(p0.x, p0.y, ah[mi][0], al[mi][0]);
            split2(p1.x, p1.y, ah[mi][1], al[mi][1]);
            split2(p2.x, p2.y, ah[mi][2], al[mi][2]);
            split2(p3.x, p3.y, ah[mi][3], al[mi][3]);
        }

#pragma unroll
        for (int ni = 0; ni < 8; ni++) {
            int col = wn * 64 + ni * 8 + (lane >> 2);
            uint32_t bh[2], bl[2];
            bh[0] = *(const uint32_t*)&Bsh[b][col * LDB + ka];
            bh[1] = *(const uint32_t*)&Bsh[b][col * LDB + ka + 8];
            bl[0] = *(const uint32_t*)&Bsl[b][col * LDB + ka];
            bl[1] = *(const uint32_t*)&Bsl[b][col * LDB + ka + 8];
#pragma unroll
            for (int mi = 0; mi < 2; mi++) {
                mma16(c[mi][ni], ah[mi], bh);
                mma16(c[mi][ni], al[mi], bh);
                mma16(c[mi][ni], ah[mi], bl);
            }
        }
        __syncthreads();
    }

    // ---- epilogue ----
#pragma unroll
    for (int mi = 0; mi < 2; mi++) {
#pragma unroll
        for (int ni = 0; ni < 8; ni++) {
            int col = wn * 64 + ni * 8 + (lane & 3) * 2;
            float bb0 = bias ? bias[col] : 0.f;
            float bb1 = bias ? bias[col + 1] : 0.f;
            int r = m_blk + wm * 32 + mi * 16 + (lane >> 2);
            if (r < M) {
                float2 v = make_float2(c[mi][ni][0] + bb0, c[mi][ni][1] + bb1);
                *(float2*)(C + (long)r * 128 + col) = v;
            }
            if (r + 8 < M) {
                float2 v = make_float2(c[mi][ni][2] + bb0, c[mi][ni][3] + bb1);
                *(float2*)(C + (long)(r + 8) * 128 + col) = v;
            }
        }
    }
}

// ============================================================
// CSR build
// ============================================================
__global__ void zero2() {
    int i = blockIdx.x * blockDim.x + threadIdx.x;
    if (i < NN) g_i[I_DEGF + i] = 0;
    else if (i < 2 * NN) g_i[I_DEGP + i - NN] = 0;
}

__global__ void count_deg2(const int* __restrict__ eif, const int* __restrict__ eip) {
    int e = blockIdx.x * blockDim.x + threadIdx.x;
    if (e < EF) {
        atomicAdd(&g_i[I_DEGF + eif[EF + e]], 1);
    } else {
        int e2 = e - EF;
        if (e2 < EP) atomicAdd(&g_i[I_DEGP + eip[EP + e2]], 1);
    }
}

// ---- 3-phase parallel exclusive scan over degrees ----
// phase A: per-block scan; off[i] = local exclusive; bsum[blk] = block total
__global__ void __launch_bounds__(1024) scanA() {
    int g = blockIdx.y;
    long deg = g ? I_DEGP : I_DEGF;
    long off = g ? I_OFFP : I_OFFF;
    long bs  = g ? I_BSP  : I_BSF;
    int i = blockIdx.x * 1024 + threadIdx.x;
    int lane = threadIdx.x & 31, wid = threadIdx.x >> 5;
    int v = (i < NN) ? g_i[deg + i] : 0;
    int x = v;
#pragma unroll
    for (int d = 1; d < 32; d <<= 1) {
        int y = __shfl_up_sync(0xffffffffu, x, d);
        if (lane >= d) x += y;
    }
    __shared__ int wsum[32];
    if (lane == 31) wsum[wid] = x;
    __syncthreads();
    if (wid == 0) {
        int y = wsum[lane];
#pragma unroll
        for (int d = 1; d < 32; d <<= 1) {
            int z = __shfl_up_sync(0xffffffffu, y, d);
            if (lane >= d) y += z;
        }
        wsum[lane] = y;
    }
    __syncthreads();
    int base = wid ? wsum[wid - 1] : 0;
    int incl = x + base;
    if (i < NN) g_i[off + i] = incl - v;      // exclusive (pre block offset)
    if (threadIdx.x == 1023) g_i[bs + blockIdx.x] = incl;
}

// phase B: exclusive scan of the NB block sums (one block per graph)
__global__ void __launch_bounds__(64) scanB() {
    long bs = blockIdx.x ? I_BSP : I_BSF;
    int t = threadIdx.x;
    int lane = t & 31, wid = t >> 5;
    int v = (t < NB) ? g_i[bs + t] : 0;
    int x = v;
#pragma unroll
    for (int d = 1; d < 32; d <<= 1) {
        int y = __shfl_up_sync(0xffffffffu, x, d);
        if (lane >= d) x += y;
    }
    __shared__ int ws[2];
    if (lane == 31) ws[wid] = x;
    __syncthreads();
    int incl = x + (wid ? ws[0] : 0);
    if (t < NB) g_i[bs + t] = incl - v;       // exclusive block offsets
}

// phase C: add block offsets; cur = off
__global__ void __launch_bounds__(1024) scanC() {
    int g = blockIdx.y;
    long off = g ? I_OFFP : I_OFFF;
    long cur = g ? I_CURP : I_CURF;
    long bs  = g ? I_BSP  : I_BSF;
    int i = blockIdx.x * 1024 + threadIdx.x;
    if (i >= NN) return;
    int v = g_i[off + i] + g_i[bs + blockIdx.x];
    g_i[off + i] = v;
    g_i[cur + i] = v;
}

__global__ void fill_csr2(const int* __restrict__ eif, const float* __restrict__ ewf,
                          const int* __restrict__ eip, const float* __restrict__ ewp) {
    int e = blockIdx.x * blockDim.x + threadIdx.x;
    if (e < EF) {
        int srcv = eif[e];
        int d = eif[EF + e];
        int pos = atomicAdd(&g_i[I_CURF + d], 1);
        g_i[I_SRCF + pos] = srcv;
        g_f[F_WF + pos] = ewf[e];
    } else {
        int e2 = e - EF;
        if (e2 >= EP) return;
        int srcv = eip[e2];
        int d = eip[EP + e2];
        int pos = atomicAdd(&g_i[I_CURP + d], 1);
        g_i[I_SRCP + pos] = srcv;
        g_f[F_WP + pos] = ewp[e2];
    }
}

// ============================================================
// GATv2, both graphs in ONE launch, one warp per dst node,
// online softmax, prefetch depth 2.
// ============================================================
__global__ void __launch_bounds__(256) gat2_kernel(
    const float* __restrict__ wedgeF, const float* __restrict__ attnF,
    const float* __restrict__ biasF,
    const float* __restrict__ wedgeP, const float* __restrict__ attnP,
    const float* __restrict__ biasP)
{
    int gw = (blockIdx.x * blockDim.x + threadIdx.x) >> 5;
    if (gw >= 2 * NN) return;
    bool isP = gw >= NN;
    int n = isP ? gw - NN : gw;
    int lane = threadIdx.x & 31;

    const float* hs   = g_f + (isP ? F_HSP : F_HSF);
    const float* hd   = g_f + (isP ? F_HDP : F_HDF);
    const float* wts  = g_f + (isP ? F_WP  : F_WF);
    const int*   off  = g_i + (isP ? I_OFFP : I_OFFF);
    const int*   degv = g_i + (isP ? I_DEGP : I_DEGF);
    const int*   srcs = g_i + (isP ? I_SRCP : I_SRCF);
    const float* wedge = isP ? wedgeP : wedgeF;
    const float* attn  = isP ? attnP  : attnF;
    const float* bias  = isP ? biasP  : biasF;
    float* out = g_f + (isP ? F_OUTP : F_OUTF);

    int begin = off[n];
    int end = begin + degv[n];

    float4 hdv = *(const float4*)(hd + (long)n * 128 + lane * 4);
    float4 wev = *(const float4*)(wedge + lane * 4);
    int h8 = lane >> 3;
    float4 av = *(const float4*)(attn + h8 * 32 + (lane & 7) * 4);

    float m = -1e30f;
    float s = 0.f;
    float a0 = 0.f, a1 = 0.f, a2 = 0.f, a3 = 0.f;

    // prefetch pipeline, depth 2
    float4 hA = make_float4(0.f,0.f,0.f,0.f), hB = hA;
    float  wA = 0.f, wB = 0.f;
    if (begin < end) {
        int sA = srcs[begin];
        wA = wts[begin];
        hA = *(const float4*)(hs + (long)sA * 128 + lane * 4);
    }
    if (begin + 1 < end) {
        int sB = srcs[begin + 1];
        wB = wts[begin + 1];
        hB = *(const float4*)(hs + (long)sB * 128 + lane * 4);
    }

    for (int p = begin; p < end; p++) {
        float4 hC = hA; float wC = wA;
        hA = hB; wA = wB;
        if (p + 2 < end) {
            int sB = srcs[p + 2];
            wB = wts[p + 2];
            hB = *(const float4*)(hs + (long)sB * 128 + lane * 4);
        }
        float z0 = hC.x + hdv.x + wC * wev.x; z0 = z0 > 0.f ? z0 : 0.2f * z0;
        float z1 = hC.y + hdv.y + wC * wev.y; z1 = z1 > 0.f ? z1 : 0.2f * z1;
        float z2 = hC.z + hdv.z + wC * wev.z; z2 = z2 > 0.f ? z2 : 0.2f * z2;
        float z3 = hC.w + hdv.w + wC * wev.w; z3 = z3 > 0.f ? z3 : 0.2f * z3;
        float part = av.x * z0 + av.y * z1 + av.z * z2 + av.w * z3;
        part += __shfl_xor_sync(0xffffffffu, part, 4);
        part += __shfl_xor_sync(0xffffffffu, part, 2);
        part += __shfl_xor_sync(0xffffffffu, part, 1);

        float mn   = fmaxf(m, part);
        float corr = __expf(m - mn);
        float pr   = __expf(part - mn);
        s  = s * corr + pr;
        a0 = a0 * corr + pr * hC.x;
        a1 = a1 * corr + pr * hC.y;
        a2 = a2 * corr + pr * hC.z;
        a3 = a3 * corr + pr * hC.w;
        m = mn;
    }

    float inv = 1.f / (s + 1e-16f);
    float4 o = make_float4(a0 * inv + bias[lane * 4],
                           a1 * inv + bias[lane * 4 + 1],
                           a2 * inv + bias[lane * 4 + 2],
                           a3 * inv + bias[lane * 4 + 3]);
    *(float4*)(out + (long)n * 128 + lane * 4) = o;
}

// ============================================================
// combine + ELU + LayerNorm: one warp per row
// ============================================================
__global__ void __launch_bounds__(256) combine_ln(
    const float* __restrict__ alpha,
    const float* __restrict__ ln_scale,
    const float* __restrict__ ln_bias,
    float* __restrict__ out)
{
    int gw = (blockIdx.x * blockDim.x + threadIdx.x) >> 5;
    if (gw >= NN) return;
    int lane = threadIdx.x & 31;
    float a = *alpha;
    const float* hf = g_f + F_OUTF + (long)gw * 128;
    const float* hp = g_f + F_OUTP + (long)gw * 128;

    float x[4];
#pragma unroll
    for (int i = 0; i < 4; i++) {
        float v = (1.f - a) * hf[lane * 4 + i] + a * hp[lane * 4 + i];
        x[i] = v > 0.f ? v : expm1f(v);
    }
    float s = x[0] + x[1] + x[2] + x[3];
#pragma unroll
    for (int o = 16; o > 0; o >>= 1) s += __shfl_xor_sync(0xffffffffu, s, o);
    float mu = s * (1.f / 128.f);
    float vs = 0.f;
#pragma unroll
    for (int i = 0; i < 4; i++) { float d = x[i] - mu; vs += d * d; }
#pragma unroll
    for (int o = 16; o > 0; o >>= 1) vs += __shfl_xor_sync(0xffffffffu, vs, o);
    float r = rsqrtf(vs * (1.f / 128.f) + 1e-6f);
#pragma unroll
    for (int i = 0; i < 4; i++) {
        int col = lane * 4 + i;
        out[(long)gw * 128 + col] = (x[i] - mu) * r * ln_scale[col] + ln_bias[col];
    }
}

// ============================================================
extern "C" void kernel_launch(void* const* d_in, const int* in_sizes, int n_in,
                              void* d_out, int out_size) {
    const float* X       = (const float*)d_in[0];
    const int*   eif     = (const int*)  d_in[1];
    const float* ewf     = (const float*)d_in[2];
    const int*   eip     = (const int*)  d_in[3];
    const float* ewp     = (const float*)d_in[4];
    const float* alpha   = (const float*)d_in[5];
    const float* ip_w    = (const float*)d_in[6];
    const float* ip_b    = (const float*)d_in[7];
    const float* gf_wsrc = (const float*)d_in[8];
    const float* gf_wdst = (const float*)d_in[9];
    const float* gf_wedge= (const float*)d_in[10];
    const float* gf_attn = (const float*)d_in[11];
    const float* gf_bias = (const float*)d_in[12];
    const float* gp_wsrc = (const float*)d_in[13];
    const float* gp_wdst = (const float*)d_in[14];
    const float* gp_wedge= (const float*)d_in[15];
    const float* gp_attn = (const float*)d_in[16];
    const float* gp_bias = (const float*)d_in[17];
    const float* ln_scale= (const float*)d_in[18];
    const float* ln_bias = (const float*)d_in[19];
    float* out = (float*)d_out;

    int gm = (NN + 127) / 128;   // 391

    // weight pre-conversion to bf16 hi/lo tiled layout
    int convN = 2000 * 128 + 4 * 128 * 128;
    convB<<<(convN + 255) / 256, 256>>>(ip_w, gf_wsrc, gf_wdst, gp_wsrc, gp_wdst);

    // CSR build: count + parallel 3-phase scan + fill
    zero2<<<(2 * NN + 255) / 256, 256>>>();
    count_deg2<<<(EF + EP + 255) / 256, 256>>>(eif, eip);
    dim3 gsc(NB, 2);
    scanA<<<gsc, 1024>>>();
    scanB<<<2, 64>>>();
    scanC<<<gsc, 1024>>>();
    fill_csr2<<<(EF + EP + 255) / 256, 256>>>(eif, ewf, eip, ewp);

    // input projection (grid.y = 1)
    dim3 g1(gm, 1);
    gemm128<<<g1, 256>>>(X, 0, B_IP, B_IP, B_IP, B_IP, ip_b, F_H, NN, 2000);

    // all 4 h-projections in ONE batched launch (grid.y = 4)
    dim3 g4(gm, 4);
    gemm128<<<g4, 256>>>(nullptr, F_H, B_GF_S, B_GF_D, B_GP_S, B_GP_D,
                         nullptr, F_HSF, NN, 128);

    // GATv2 on BOTH graphs in one launch
    int gg2 = (2 * NN * 32 + 255) / 256;
    gat2_kernel<<<gg2, 256>>>(gf_wedge, gf_attn, gf_bias,
                              gp_wedge, gp_attn, gp_bias);

    // combine + elu + layernorm
    int gg = (NN * 32 + 255) / 256;
    combine_ln<<<gg, 256>>>(alpha, ln_scale, ln_bias, out);
}